// round 2
// baseline (speedup 1.0000x reference)
#include <cuda_runtime.h>
#include <math.h>

// ---------------- problem constants ----------------
#define BB   4
#define TT   2048
#define DIM  1024
#define HH   16
#define HD   64
#define MR   (BB*TT)        // 8192 rows
#define NQKV 3072

// ---------------- scratch (device globals; no allocation) ----------------
__device__ float g_qkv[(size_t)MR * NQKV];   // 96 MB: [row, 0:1024)=q [1024:2048)=k [2048:3072)=v
__device__ float g_att[(size_t)MR * DIM];    // 32 MB: attention output, (b,t,h,hd) contiguous

// ---------------- fp32 SGEMM: C[M,N] = A[M,K] @ B[K,N], 128x128x8, 8x8/thread ----------------
__global__ __launch_bounds__(256) void sgemm128(const float* __restrict__ A,
                                                const float* __restrict__ B,
                                                float* __restrict__ C,
                                                int M, int N, int K)
{
    __shared__ float As[8][128];
    __shared__ float Bs[8][128];
    const int tid = threadIdx.x;
    const int bx = blockIdx.x, by = blockIdx.y;
    const int arow = tid >> 1, acol = (tid & 1) << 2;   // 128 rows x 8 cols, 1 float4/thread
    const int brow = tid >> 5, bcol = (tid & 31) << 2;  // 8 rows x 128 cols, 1 float4/thread
    const int tx = tid & 15, ty = tid >> 4;

    const float* Ap = A + (size_t)(by * 128 + arow) * K + acol;
    const float* Bp = B + (size_t)brow * N + bx * 128 + bcol;

    float acc[8][8];
    #pragma unroll
    for (int i = 0; i < 8; i++)
        #pragma unroll
        for (int j = 0; j < 8; j++) acc[i][j] = 0.f;

    for (int k0 = 0; k0 < K; k0 += 8) {
        float4 av = *(const float4*)(Ap + k0);
        float4 bv = *(const float4*)(Bp + (size_t)k0 * N);
        As[acol + 0][arow] = av.x;
        As[acol + 1][arow] = av.y;
        As[acol + 2][arow] = av.z;
        As[acol + 3][arow] = av.w;
        *(float4*)&Bs[brow][bcol] = bv;
        __syncthreads();
        #pragma unroll
        for (int kk = 0; kk < 8; kk++) {
            float a[8], b[8];
            *(float4*)(a)     = *(const float4*)&As[kk][ty * 8];
            *(float4*)(a + 4) = *(const float4*)&As[kk][ty * 8 + 4];
            *(float4*)(b)     = *(const float4*)&Bs[kk][tx * 8];
            *(float4*)(b + 4) = *(const float4*)&Bs[kk][tx * 8 + 4];
            #pragma unroll
            for (int i = 0; i < 8; i++)
                #pragma unroll
                for (int j = 0; j < 8; j++)
                    acc[i][j] = fmaf(a[i], b[j], acc[i][j]);
        }
        __syncthreads();
    }
    #pragma unroll
    for (int i = 0; i < 8; i++) {
        float* Cp = C + (size_t)(by * 128 + ty * 8 + i) * N + bx * 128 + tx * 8;
        *(float4*)Cp       = make_float4(acc[i][0], acc[i][1], acc[i][2], acc[i][3]);
        *(float4*)(Cp + 4) = make_float4(acc[i][4], acc[i][5], acc[i][6], acc[i][7]);
    }
}

// ---------------- RoPE in-place on q,k segments of g_qkv ----------------
__global__ void rope_kernel(const float* __restrict__ cosb, const float* __restrict__ sinb)
{
    const int total = MR * HH * (HD / 2);     // 4,194,304 pairs per tensor
    int idx = blockIdx.x * blockDim.x + threadIdx.x;
    if (idx >= 2 * total) return;
    int seg = (idx >= total) ? 1 : 0;         // 0 = q, 1 = k
    int p = idx - seg * total;
    int d  = p & 31;                           // pair index within head (HD/2=32)
    int h  = (p >> 5) & 15;
    int bt = p >> 9;                           // (b*T + t)
    int t  = bt & (TT - 1);
    size_t addr = (size_t)bt * NQKV + seg * 1024 + h * 64 + (d << 1);
    float e = g_qkv[addr], o = g_qkv[addr + 1];
    float c = cosb[t * 32 + d], s = sinb[t * 32 + d];
    g_qkv[addr]     = e * c - o * s;
    g_qkv[addr + 1] = e * s + o * c;
}

// ---------------- streaming (flash) attention, fp32 ----------------
// grid: (T/64, B*H); block: 256 threads. Each block: one 64-row Q tile of one (b,h).
// Thread (tx = tid&15, ty = tid>>4): q-rows ty*4+i (i<4), key-cols / out-dims tx + 16*j (j<4).
#define SMPAD 68
__global__ __launch_bounds__(256) void flash64()
{
    extern __shared__ float sm[];
    float* Qs = sm;                    // 64 x 68
    float* Ks = Qs + 64 * SMPAD;
    float* Vs = Ks + 64 * SMPAD;
    float* Ps = Vs + 64 * SMPAD;

    const int tid = threadIdx.x;
    const int tx = tid & 15, ty = tid >> 4;
    const int b = blockIdx.y >> 4, h = blockIdx.y & 15;
    const int t0 = blockIdx.x << 6;

    const size_t qbase = ((size_t)(b * TT + t0)) * NQKV + h * 64;
    const float scale = 0.125f;   // HD^-0.5

    // Load + pre-scale Q tile
    #pragma unroll
    for (int it = 0; it < 4; it++) {
        int f = tid + it * 256;
        int r = f >> 4, c4 = (f & 15) << 2;
        float4 v = *(const float4*)(g_qkv + qbase + (size_t)r * NQKV + c4);
        v.x *= scale; v.y *= scale; v.z *= scale; v.w *= scale;
        *(float4*)(Qs + r * SMPAD + c4) = v;
    }

    float m[4], l[4], acc[4][4];
    #pragma unroll
    for (int i = 0; i < 4; i++) {
        m[i] = -INFINITY; l[i] = 0.f;
        #pragma unroll
        for (int j = 0; j < 4; j++) acc[i][j] = 0.f;
    }

    for (int kt = 0; kt < 32; kt++) {
        __syncthreads();   // protect Ks/Vs/Ps from previous iteration's readers
        const size_t kbase = ((size_t)(b * TT + kt * 64)) * NQKV + 1024 + h * 64;
        #pragma unroll
        for (int it = 0; it < 4; it++) {
            int f = tid + it * 256;
            int r = f >> 4, c4 = (f & 15) << 2;
            *(float4*)(Ks + r * SMPAD + c4) = *(const float4*)(g_qkv + kbase + (size_t)r * NQKV + c4);
            *(float4*)(Vs + r * SMPAD + c4) = *(const float4*)(g_qkv + kbase + 1024 + (size_t)r * NQKV + c4);
        }
        __syncthreads();

        // S = Q K^T (4x4 microtile)
        float s[4][4];
        #pragma unroll
        for (int i = 0; i < 4; i++)
            #pragma unroll
            for (int j = 0; j < 4; j++) s[i][j] = 0.f;
        #pragma unroll 8
        for (int dd = 0; dd < 64; dd++) {
            float a[4], bb[4];
            #pragma unroll
            for (int i = 0; i < 4; i++) a[i]  = Qs[(ty * 4 + i) * SMPAD + dd];
            #pragma unroll
            for (int j = 0; j < 4; j++) bb[j] = Ks[(tx + j * 16) * SMPAD + dd];
            #pragma unroll
            for (int i = 0; i < 4; i++)
                #pragma unroll
                for (int j = 0; j < 4; j++)
                    s[i][j] = fmaf(a[i], bb[j], s[i][j]);
        }

        // online softmax stats + P to smem
        #pragma unroll
        for (int i = 0; i < 4; i++) {
            float rm = fmaxf(fmaxf(s[i][0], s[i][1]), fmaxf(s[i][2], s[i][3]));
            rm = fmaxf(rm, __shfl_xor_sync(0xffffffffu, rm, 1));
            rm = fmaxf(rm, __shfl_xor_sync(0xffffffffu, rm, 2));
            rm = fmaxf(rm, __shfl_xor_sync(0xffffffffu, rm, 4));
            rm = fmaxf(rm, __shfl_xor_sync(0xffffffffu, rm, 8));
            float mnew = fmaxf(m[i], rm);
            float corr = __expf(m[i] - mnew);
            float psum = 0.f;
            #pragma unroll
            for (int j = 0; j < 4; j++) {
                float p = __expf(s[i][j] - mnew);
                Ps[(ty * 4 + i) * SMPAD + tx + j * 16] = p;
                psum += p;
            }
            psum += __shfl_xor_sync(0xffffffffu, psum, 1);
            psum += __shfl_xor_sync(0xffffffffu, psum, 2);
            psum += __shfl_xor_sync(0xffffffffu, psum, 4);
            psum += __shfl_xor_sync(0xffffffffu, psum, 8);
            l[i] = l[i] * corr + psum;
            #pragma unroll
            for (int j = 0; j < 4; j++) acc[i][j] *= corr;
            m[i] = mnew;
        }
        __syncthreads();

        // O += P V (4x4 microtile)
        #pragma unroll 8
        for (int jj = 0; jj < 64; jj++) {
            float p[4], v[4];
            #pragma unroll
            for (int i = 0; i < 4; i++) p[i] = Ps[(ty * 4 + i) * SMPAD + jj];
            #pragma unroll
            for (int j = 0; j < 4; j++) v[j] = Vs[jj * SMPAD + tx + j * 16];
            #pragma unroll
            for (int i = 0; i < 4; i++)
                #pragma unroll
                for (int j = 0; j < 4; j++)
                    acc[i][j] = fmaf(p[i], v[j], acc[i][j]);
        }
    }

    // epilogue: normalize, write (b,t,h,hd)-contiguous
    #pragma unroll
    for (int i = 0; i < 4; i++) {
        float inv = 1.f / l[i];
        size_t obase = ((size_t)(b * TT + t0 + ty * 4 + i)) * DIM + h * 64;
        #pragma unroll
        for (int j = 0; j < 4; j++)
            g_att[obase + tx + j * 16] = acc[i][j] * inv;
    }
}

// ---------------- launch ----------------
extern "C" void kernel_launch(void* const* d_in, const int* in_sizes, int n_in,
                              void* d_out, int out_size)
{
    const float* x     = (const float*)d_in[0];
    const float* fcos  = (const float*)d_in[1];
    const float* fsin  = (const float*)d_in[2];
    // d_in[3] = mask (all true) — intentionally unused
    const float* Wqkv  = (const float*)d_in[4];
    const float* Wproj = (const float*)d_in[5];
    float* out = (float*)d_out;

    float *qkv_ptr, *att_ptr;
    cudaGetSymbolAddress((void**)&qkv_ptr, g_qkv);
    cudaGetSymbolAddress((void**)&att_ptr, g_att);

    // 1) QKV = x @ Wqkv   [8192,1024] @ [1024,3072]
    sgemm128<<<dim3(NQKV / 128, MR / 128), 256>>>(x, Wqkv, qkv_ptr, MR, NQKV, DIM);

    // 2) RoPE on q,k in place
    {
        int total2 = 2 * MR * HH * (HD / 2);
        rope_kernel<<<(total2 + 255) / 256, 256>>>(fcos, fsin);
    }

    // 3) flash attention
    {
        const int smem = 4 * 64 * SMPAD * (int)sizeof(float); // 69632 B
        cudaFuncSetAttribute(flash64, cudaFuncAttributeMaxDynamicSharedMemorySize, smem);
        flash64<<<dim3(TT / 64, BB * HH), 256, smem>>>();
    }

    // 4) out = att @ Wproj   [8192,1024] @ [1024,1024]
    sgemm128<<<dim3(DIM / 128, MR / 128), 256>>>(att_ptr, Wproj, out, MR, DIM, DIM);
}

// round 5
// speedup vs baseline: 2.4839x; 2.4839x over previous
#include <cuda_runtime.h>
#include <math.h>

// ---------------- problem constants ----------------
#define BB   4
#define TT   2048
#define DIM  1024
#define HH   16
#define HD   64
#define MR   (BB*TT)        // 8192 rows
#define NQKV 3072

// ---------------- scratch (device globals; no allocation) ----------------
__device__ float g_qkv[(size_t)MR * NQKV];   // 96 MB
__device__ float g_att[(size_t)MR * DIM];    // 32 MB

// ---------------- helpers ----------------
__device__ __forceinline__ unsigned f2tf32(float f) {
    unsigned u;
    asm("cvt.rna.tf32.f32 %0, %1;" : "=r"(u) : "f"(f));
    return u;
}

__device__ __forceinline__ void mma8(float c[4],
                                     unsigned a0, unsigned a1, unsigned a2, unsigned a3,
                                     unsigned b0, unsigned b1) {
    asm volatile(
        "mma.sync.aligned.m16n8k8.row.col.f32.tf32.tf32.f32 "
        "{%0,%1,%2,%3}, {%4,%5,%6,%7}, {%8,%9}, {%0,%1,%2,%3};\n"
        : "+f"(c[0]), "+f"(c[1]), "+f"(c[2]), "+f"(c[3])
        : "r"(a0), "r"(a1), "r"(a2), "r"(a3), "r"(b0), "r"(b1));
}

// ============================================================================
// tf32 GEMM: C[M,N] = A[M,K] @ B[K,N].  128x128 block tile, k-step 16.
// 8 warps as 2(M) x 4(N); warp tile 64x32 = 4x4 m16n8k8 tiles.
// ============================================================================
#define GP 132   // smem row pitch (conflict-free fragment loads)
__global__ __launch_bounds__(256) void gemm_tf32(const float* __restrict__ A,
                                                 const float* __restrict__ B,
                                                 float* __restrict__ C,
                                                 int M, int N, int K)
{
    __shared__ unsigned As[16][GP];   // [k][m]
    __shared__ unsigned Bs[16][GP];   // [k][n]

    const int tid = threadIdx.x;
    const int lane = tid & 31, wid = tid >> 5;
    const int g = lane >> 2, t = lane & 3;
    const int wm = wid & 1, wn = wid >> 1;
    const int bx = blockIdx.x, by = blockIdx.y;

    // global load mapping
    const int ar = tid >> 2, ac = (tid & 3) << 2;     // A: 64 rows/pass x 16 cols
    const int br = tid >> 5, bc = (tid & 31) << 2;    // B: 8 rows/pass x 128 cols
    const float* Ap = A + (size_t)(by * 128 + ar) * K + ac;
    const float* Bp = B + (size_t)br * N + bx * 128 + bc;

    float4 ra[2], rb[2];
    ra[0] = *(const float4*)(Ap);
    ra[1] = *(const float4*)(Ap + (size_t)64 * K);
    rb[0] = *(const float4*)(Bp);
    rb[1] = *(const float4*)(Bp + (size_t)8 * N);

    float acc[4][4][4];
    #pragma unroll
    for (int mt = 0; mt < 4; mt++)
        #pragma unroll
        for (int nt = 0; nt < 4; nt++)
            #pragma unroll
            for (int i = 0; i < 4; i++) acc[mt][nt][i] = 0.f;

    const int KB = K >> 4;
    for (int kb = 0; kb < KB; kb++) {
        // store staged tile (transpose A to [k][m])
        #pragma unroll
        for (int i = 0; i < 2; i++) {
            As[ac + 0][ar + 64 * i] = f2tf32(ra[i].x);
            As[ac + 1][ar + 64 * i] = f2tf32(ra[i].y);
            As[ac + 2][ar + 64 * i] = f2tf32(ra[i].z);
            As[ac + 3][ar + 64 * i] = f2tf32(ra[i].w);
            uint4 bv;
            bv.x = f2tf32(rb[i].x); bv.y = f2tf32(rb[i].y);
            bv.z = f2tf32(rb[i].z); bv.w = f2tf32(rb[i].w);
            *(uint4*)&Bs[br + 8 * i][bc] = bv;
        }
        __syncthreads();

        if (kb + 1 < KB) {
            int k0 = (kb + 1) << 4;
            ra[0] = *(const float4*)(Ap + k0);
            ra[1] = *(const float4*)(Ap + (size_t)64 * K + k0);
            rb[0] = *(const float4*)(Bp + (size_t)k0 * N);
            rb[1] = *(const float4*)(Bp + (size_t)(k0 + 8) * N);
        }

        #pragma unroll
        for (int ks = 0; ks < 2; ks++) {
            unsigned a[4][4], b[4][2];
            #pragma unroll
            for (int mt = 0; mt < 4; mt++) {
                int row = wm * 64 + mt * 16;
                a[mt][0] = As[8 * ks + t][row + g];
                a[mt][1] = As[8 * ks + t][row + g + 8];
                a[mt][2] = As[8 * ks + t + 4][row + g];
                a[mt][3] = As[8 * ks + t + 4][row + g + 8];
            }
            #pragma unroll
            for (int nt = 0; nt < 4; nt++) {
                int col = wn * 32 + nt * 8;
                b[nt][0] = Bs[8 * ks + t][col + g];
                b[nt][1] = Bs[8 * ks + t + 4][col + g];
            }
            #pragma unroll
            for (int mt = 0; mt < 4; mt++)
                #pragma unroll
                for (int nt = 0; nt < 4; nt++)
                    mma8(acc[mt][nt], a[mt][0], a[mt][1], a[mt][2], a[mt][3],
                         b[nt][0], b[nt][1]);
        }
        __syncthreads();
    }

    // epilogue
    #pragma unroll
    for (int mt = 0; mt < 4; mt++) {
        int row = by * 128 + wm * 64 + mt * 16 + g;
        #pragma unroll
        for (int nt = 0; nt < 4; nt++) {
            int col = bx * 128 + wn * 32 + nt * 8 + 2 * t;
            *(float2*)&C[(size_t)row * N + col]       = make_float2(acc[mt][nt][0], acc[mt][nt][1]);
            *(float2*)&C[(size_t)(row + 8) * N + col] = make_float2(acc[mt][nt][2], acc[mt][nt][3]);
        }
    }
}

// ---------------- RoPE in-place on q,k segments of g_qkv ----------------
__global__ void rope_kernel(const float* __restrict__ cosb, const float* __restrict__ sinb)
{
    const int total = MR * HH * (HD / 2);
    int idx = blockIdx.x * blockDim.x + threadIdx.x;
    if (idx >= 2 * total) return;
    int seg = (idx >= total) ? 1 : 0;
    int p = idx - seg * total;
    int d  = p & 31;
    int h  = (p >> 5) & 15;
    int bt = p >> 9;
    int t  = bt & (TT - 1);
    size_t addr = (size_t)bt * NQKV + seg * 1024 + h * 64 + (d << 1);
    float e = g_qkv[addr], o = g_qkv[addr + 1];
    float c = cosb[t * 32 + d], s = sinb[t * 32 + d];
    g_qkv[addr]     = e * c - o * s;
    g_qkv[addr + 1] = e * s + o * c;
}

// ============================================================================
// flash attention with tf32 mma.  Q-tile 128, key-tile 64, 8 warps.
// Warp w owns S/O rows 16w..16w+15.  Q fragments resident in registers.
// ============================================================================
#define FP 68    // smem row pitch
__global__ __launch_bounds__(256) void flash_mma()
{
    extern __shared__ unsigned smu[];
    unsigned* Qs = smu;                 // 128 x FP (tf32), reused as P buffer
    unsigned* Ks = smu + 128 * FP;      // 64 x FP
    unsigned* Vs = Ks + 64 * FP;        // 64 x FP

    const int tid = threadIdx.x;
    const int lane = tid & 31, w = tid >> 5;
    const int g = lane >> 2, t = lane & 3;
    const int b = blockIdx.y >> 4, h = blockIdx.y & 15;
    const int t0 = blockIdx.x << 7;     // 128-row q tile

    const float scale = 0.125f;

    // ---- stage Q (scaled, tf32) ----
    const size_t qbase = ((size_t)(b * TT + t0)) * NQKV + h * 64;
    #pragma unroll
    for (int it = 0; it < 8; it++) {
        int f = tid + it * 256;
        int r = f >> 4, c4 = (f & 15) << 2;
        float4 v = *(const float4*)(g_qkv + qbase + (size_t)r * NQKV + c4);
        uint4 u;
        u.x = f2tf32(v.x * scale); u.y = f2tf32(v.y * scale);
        u.z = f2tf32(v.z * scale); u.w = f2tf32(v.w * scale);
        *(uint4*)&Qs[r * FP + c4] = u;
    }
    __syncthreads();

    // ---- Q fragments to registers (8 k-steps x 4) ----
    unsigned qa[8][4];
    #pragma unroll
    for (int ks = 0; ks < 8; ks++) {
        int ra = (16 * w + g) * FP, rb = (16 * w + g + 8) * FP;
        qa[ks][0] = Qs[ra + 8 * ks + t];
        qa[ks][1] = Qs[rb + 8 * ks + t];
        qa[ks][2] = Qs[ra + 8 * ks + t + 4];
        qa[ks][3] = Qs[rb + 8 * ks + t + 4];
    }

    float m_a = -INFINITY, m_b = -INFINITY, l_a = 0.f, l_b = 0.f;
    float oacc[8][4];
    #pragma unroll
    for (int nt = 0; nt < 8; nt++)
        #pragma unroll
        for (int i = 0; i < 4; i++) oacc[nt][i] = 0.f;

    for (int kt = 0; kt < 32; kt++) {
        __syncthreads();   // previous iter's smem reads done (also covers Q frag load)
        // ---- stage K,V tile (64x64 each, tf32) ----
        const size_t kbase = ((size_t)(b * TT + kt * 64)) * NQKV + 1024 + h * 64;
        float4 kv[8];
        #pragma unroll
        for (int it = 0; it < 4; it++) {
            int f = tid + it * 256;
            int r = f >> 4, c4 = (f & 15) << 2;
            kv[it]     = *(const float4*)(g_qkv + kbase + (size_t)r * NQKV + c4);
            kv[4 + it] = *(const float4*)(g_qkv + kbase + 1024 + (size_t)r * NQKV + c4);
        }
        #pragma unroll
        for (int it = 0; it < 4; it++) {
            int f = tid + it * 256;
            int r = f >> 4, c4 = (f & 15) << 2;
            uint4 uk, uv;
            uk.x = f2tf32(kv[it].x); uk.y = f2tf32(kv[it].y);
            uk.z = f2tf32(kv[it].z); uk.w = f2tf32(kv[it].w);
            uv.x = f2tf32(kv[4 + it].x); uv.y = f2tf32(kv[4 + it].y);
            uv.z = f2tf32(kv[4 + it].z); uv.w = f2tf32(kv[4 + it].w);
            *(uint4*)&Ks[r * FP + c4] = uk;
            *(uint4*)&Vs[r * FP + c4] = uv;
        }
        __syncthreads();

        // ---- S = Q K^T : warp rows 16w..16w+15, cols 0..63 ----
        float sc[8][4];
        #pragma unroll
        for (int nt = 0; nt < 8; nt++)
            #pragma unroll
            for (int i = 0; i < 4; i++) sc[nt][i] = 0.f;
        #pragma unroll
        for (int ks = 0; ks < 8; ks++) {
            #pragma unroll
            for (int nt = 0; nt < 8; nt++) {
                unsigned b0 = Ks[(8 * nt + g) * FP + 8 * ks + t];
                unsigned b1 = Ks[(8 * nt + g) * FP + 8 * ks + t + 4];
                mma8(sc[nt], qa[ks][0], qa[ks][1], qa[ks][2], qa[ks][3], b0, b1);
            }
        }

        // ---- online softmax (rows: g and g+8 of this warp's 16) ----
        float vmax_a = -INFINITY, vmax_b = -INFINITY;
        #pragma unroll
        for (int nt = 0; nt < 8; nt++) {
            vmax_a = fmaxf(vmax_a, fmaxf(sc[nt][0], sc[nt][1]));
            vmax_b = fmaxf(vmax_b, fmaxf(sc[nt][2], sc[nt][3]));
        }
        vmax_a = fmaxf(vmax_a, __shfl_xor_sync(0xffffffffu, vmax_a, 1));
        vmax_a = fmaxf(vmax_a, __shfl_xor_sync(0xffffffffu, vmax_a, 2));
        vmax_b = fmaxf(vmax_b, __shfl_xor_sync(0xffffffffu, vmax_b, 1));
        vmax_b = fmaxf(vmax_b, __shfl_xor_sync(0xffffffffu, vmax_b, 2));

        float mn_a = fmaxf(m_a, vmax_a), mn_b = fmaxf(m_b, vmax_b);
        float corr_a = __expf(m_a - mn_a), corr_b = __expf(m_b - mn_b);
        m_a = mn_a; m_b = mn_b;

        float psum_a = 0.f, psum_b = 0.f;
        #pragma unroll
        for (int nt = 0; nt < 8; nt++) {
            unsigned p0 = f2tf32(__expf(sc[nt][0] - mn_a));
            unsigned p1 = f2tf32(__expf(sc[nt][1] - mn_a));
            unsigned p2 = f2tf32(__expf(sc[nt][2] - mn_b));
            unsigned p3 = f2tf32(__expf(sc[nt][3] - mn_b));
            psum_a += __uint_as_float(p0) + __uint_as_float(p1);
            psum_b += __uint_as_float(p2) + __uint_as_float(p3);
            // store P (tf32 bits) to smem: rows 16w+g / 16w+g+8, cols 8nt+2t
            *(uint2*)&Qs[(16 * w + g) * FP + 8 * nt + 2 * t]     = make_uint2(p0, p1);
            *(uint2*)&Qs[(16 * w + g + 8) * FP + 8 * nt + 2 * t] = make_uint2(p2, p3);
        }
        psum_a += __shfl_xor_sync(0xffffffffu, psum_a, 1);
        psum_a += __shfl_xor_sync(0xffffffffu, psum_a, 2);
        psum_b += __shfl_xor_sync(0xffffffffu, psum_b, 1);
        psum_b += __shfl_xor_sync(0xffffffffu, psum_b, 2);
        l_a = l_a * corr_a + psum_a;
        l_b = l_b * corr_b + psum_b;

        // rescale existing O accumulator
        #pragma unroll
        for (int nt = 0; nt < 8; nt++) {
            oacc[nt][0] *= corr_a; oacc[nt][1] *= corr_a;
            oacc[nt][2] *= corr_b; oacc[nt][3] *= corr_b;
        }
        __syncwarp();   // P stores visible to all lanes of this warp

        // ---- O += P V ----
        #pragma unroll
        for (int ks = 0; ks < 8; ks++) {
            unsigned pa0 = Qs[(16 * w + g) * FP + 8 * ks + t];
            unsigned pa1 = Qs[(16 * w + g + 8) * FP + 8 * ks + t];
            unsigned pa2 = Qs[(16 * w + g) * FP + 8 * ks + t + 4];
            unsigned pa3 = Qs[(16 * w + g + 8) * FP + 8 * ks + t + 4];
            #pragma unroll
            for (int nt = 0; nt < 8; nt++) {
                unsigned b0 = Vs[(8 * ks + t) * FP + 8 * nt + g];
                unsigned b1 = Vs[(8 * ks + t + 4) * FP + 8 * nt + g];
                mma8(oacc[nt], pa0, pa1, pa2, pa3, b0, b1);
            }
        }
    }

    // ---- epilogue ----
    float inv_a = 1.f / l_a, inv_b = 1.f / l_b;
    size_t row_a = (size_t)(b * TT + t0 + 16 * w + g) * DIM + h * 64;
    size_t row_b = (size_t)(b * TT + t0 + 16 * w + g + 8) * DIM + h * 64;
    #pragma unroll
    for (int nt = 0; nt < 8; nt++) {
        int col = 8 * nt + 2 * t;
        *(float2*)&g_att[row_a + col] = make_float2(oacc[nt][0] * inv_a, oacc[nt][1] * inv_a);
        *(float2*)&g_att[row_b + col] = make_float2(oacc[nt][2] * inv_b, oacc[nt][3] * inv_b);
    }
}

// ---------------- launch ----------------
extern "C" void kernel_launch(void* const* d_in, const int* in_sizes, int n_in,
                              void* d_out, int out_size)
{
    const float* x     = (const float*)d_in[0];
    const float* fcos  = (const float*)d_in[1];
    const float* fsin  = (const float*)d_in[2];
    // d_in[3] = mask (all true) — unused
    const float* Wqkv  = (const float*)d_in[4];
    const float* Wproj = (const float*)d_in[5];
    float* out = (float*)d_out;

    float *qkv_ptr, *att_ptr;
    cudaGetSymbolAddress((void**)&qkv_ptr, g_qkv);
    cudaGetSymbolAddress((void**)&att_ptr, g_att);

    // 1) QKV = x @ Wqkv
    gemm_tf32<<<dim3(NQKV / 128, MR / 128), 256>>>(x, Wqkv, qkv_ptr, MR, NQKV, DIM);

    // 2) RoPE
    {
        int total2 = 2 * MR * HH * (HD / 2);
        rope_kernel<<<(total2 + 255) / 256, 256>>>(fcos, fsin);
    }

    // 3) flash attention (tf32 mma)
    {
        const int smem = (128 + 64 + 64) * FP * (int)sizeof(unsigned); // 69632 B
        cudaFuncSetAttribute(flash_mma, cudaFuncAttributeMaxDynamicSharedMemorySize, smem);
        flash_mma<<<dim3(TT / 128, BB * HH), 256, smem>>>();
    }

    // 4) out = att @ Wproj
    gemm_tf32<<<dim3(DIM / 128, MR / 128), 256>>>(att_ptr, Wproj, out, MR, DIM, DIM);
}